// round 4
// baseline (speedup 1.0000x reference)
#include <cuda_runtime.h>

#define HVAL 256
#define HINGE 100.0f

__device__ __forceinline__ float safe_sqrt(float x) {
    return x > 0.0f ? sqrtf(x) : 0.0f;
}

__global__ __launch_bounds__(256, 5)
void traj_cost_kernel(const float* __restrict__ pos,   // [B,H,3]
                      const float* __restrict__ rot,   // [B,H,3,3]
                      const float* __restrict__ gpos,  // [H,3]
                      const float* __restrict__ grot,  // [H,3,3]
                      float* __restrict__ out,         // [3,B*H] (cost, rot_err_norm, goal_dist)
                      int B)
{
    __shared__ float s_rot[HVAL * 9];   // 2304 floats = 576 float4 = 9 KB... (36 KB bytes)
    __shared__ float s_pos[HVAL * 3];   // 768 floats = 192 float4

    const int b   = blockIdx.x;
    const int tid = threadIdx.x;

    // --- Coalesced float4 staging of this block's rot/pos tile ---
    {
        const float4* rsrc = reinterpret_cast<const float4*>(rot + (size_t)b * HVAL * 9);
        float4* rdst = reinterpret_cast<float4*>(s_rot);
        // 2304 floats = 576 float4: 2 full passes + 64-thread tail
        rdst[tid]       = rsrc[tid];
        rdst[tid + 256] = rsrc[tid + 256];
        if (tid < 64) rdst[tid + 512] = rsrc[tid + 512];

        const float4* psrc = reinterpret_cast<const float4*>(pos + (size_t)b * HVAL * 3);
        float4* pdst = reinterpret_cast<float4*>(s_pos);
        // 768 floats = 192 float4
        if (tid < 192) pdst[tid] = psrc[tid];
    }
    __syncthreads();

    const int h = tid;

    // Per-thread operands (stride 9 / 3 floats across threads: odd strides -> conflict-free)
    float R[9], p[3], G[9], pg[3];
    #pragma unroll
    for (int i = 0; i < 9; i++) R[i] = s_rot[h * 9 + i];
    #pragma unroll
    for (int i = 0; i < 3; i++) p[i] = s_pos[h * 3 + i];
    #pragma unroll
    for (int i = 0; i < 9; i++) G[i] = __ldg(&grot[h * 9 + i]);
    #pragma unroll
    for (int i = 0; i < 3; i++) pg[i] = __ldg(&gpos[h * 3 + i]);

    // ee_t_g[i] = (R^T p)[i] - (G^T pg)[i]
    float t[3];
    #pragma unroll
    for (int i = 0; i < 3; i++) {
        float eto = fmaf(R[i], p[0], fmaf(R[3 + i], p[1], R[6 + i] * p[2]));
        float otg = fmaf(G[i], pg[0], fmaf(G[3 + i], pg[1], G[6 + i] * pg[2]));
        t[i] = eto - otg;
    }
    float pos_err = fmaf(t[0], t[0], fmaf(t[1], t[1], t[2] * t[2]));
    float goal_dist = safe_sqrt(pos_err);

    // ee_R_g[i][j] = sum_k G[k][i] * R[k][j] ; d = I - ee_R_g ; row_norm[i] = ||d[i,:]||
    float rn[3];
    #pragma unroll
    for (int i = 0; i < 3; i++) {
        float rsq = 0.0f;
        #pragma unroll
        for (int j = 0; j < 3; j++) {
            float m = fmaf(G[i], R[j], fmaf(G[3 + i], R[3 + j], G[6 + i] * R[6 + j]));
            float d = (i == j ? 1.0f : 0.0f) - m;
            rsq = fmaf(d, d, rsq);
        }
        rn[i] = safe_sqrt(rsq);
    }

    float rn_sum = rn[0] + rn[1] + rn[2];
    float rot_err_norm = safe_sqrt(fmaf(rn[0], rn[0], fmaf(rn[1], rn[1], rn[2] * rn[2])));
    float rot_err = rn_sum * rn_sum;
    if (goal_dist > HINGE) rot_err = 0.0f;
    // CONVERGENCE thresholds are 0.0 -> (x < 0) never true for nonneg values: no-op.

    float cost = safe_sqrt(rot_err) + safe_sqrt(pos_err);

    const size_t BH = (size_t)B * HVAL;
    const size_t n  = (size_t)b * HVAL + h;
    out[n]          = cost;
    out[BH + n]     = rot_err_norm;
    out[2 * BH + n] = goal_dist;
}

extern "C" void kernel_launch(void* const* d_in, const int* in_sizes, int n_in,
                              void* d_out, int out_size) {
    // Bind inputs BY SIZE (robust to harness ordering):
    //   H*3 (smallest)  -> ee_goal_pos_traj
    //   H*9             -> ee_goal_rot_traj
    //   B*H*3           -> ee_pos_batch
    //   B*H*9 (largest) -> ee_rot_batch
    int idx[4] = {0, 1, 2, 3};
    for (int i = 1; i < 4; i++) {
        int v = idx[i];
        int j = i - 1;
        while (j >= 0 && in_sizes[idx[j]] > in_sizes[v]) { idx[j + 1] = idx[j]; j--; }
        idx[j + 1] = v;
    }
    const float* gpos = (const float*)d_in[idx[0]];  // H*3
    const float* grot = (const float*)d_in[idx[1]];  // H*9
    const float* pos  = (const float*)d_in[idx[2]];  // B*H*3
    const float* rot  = (const float*)d_in[idx[3]];  // B*H*9

    const int H = in_sizes[idx[0]] / 3;              // 256
    const int B = in_sizes[idx[3]] / (9 * H);        // 8192

    float* out = (float*)d_out;
    traj_cost_kernel<<<B, 256>>>(pos, rot, gpos, grot, out, B);
}